// round 6
// baseline (speedup 1.0000x reference)
#include <cuda_runtime.h>
#include <cuda_bf16.h>

#define N_MAX 100000
#define E_MAX 1600000
#define NB_SCAN 128

// ---------------- device scratch ----------------
__device__ int    g_flag;                 // 1 = edge_index is int64
__device__ float  g_expsum[N_MAX];
__device__ int    g_count[N_MAX];
__device__ int    g_fill[N_MAX];
__device__ int    g_off[N_MAX + 1];
__device__ unsigned long long g_partial[NB_SCAN];   // lookback state
__device__ float2 g_edge[E_MAX];          // {bits(src*64), exp(attr)} CSR by dst
__device__ float  g_xw[N_MAX * 64];       // layer-1 XW
__device__ float  g_xw2[N_MAX * 64];      // layer-2 XW (separate: no race w/ agg1)
__device__ float  g_h1[N_MAX * 64];

// ---------------- f32x2 packed fma ----------------
__device__ __forceinline__ void ffma2(unsigned long long& d,
                                      unsigned long long a,
                                      unsigned long long b) {
    asm("fma.rn.f32x2 %0, %1, %2, %0;" : "+l"(d) : "l"(a), "l"(b));
}
__device__ __forceinline__ float f32x2_hsum(unsigned long long v) {
    unsigned int lo, hi;
    asm("mov.b64 {%0, %1}, %2;" : "=r"(lo), "=r"(hi) : "l"(v));
    return __uint_as_float(lo) + __uint_as_float(hi);
}

// ---------------- fused zero + dtype detect ----------------
// last block: detect (int64 LE with values <100000 => odd 32-bit words all 0)
// and zero scan state; other blocks: zero per-node accumulators.
__global__ void zero_detect_kernel(const int* __restrict__ p, int N) {
    if (blockIdx.x == gridDim.x - 1) {
        __shared__ int cnt;
        if (threadIdx.x == 0) cnt = 0;
        __syncthreads();
        int nz = 0;
        for (int i = threadIdx.x; i < 4096; i += blockDim.x)
            if (p[2 * i + 1] != 0) nz++;
        atomicAdd(&cnt, nz);
        __syncthreads();
        if (threadIdx.x == 0) g_flag = (cnt < 64) ? 1 : 0;
        if (threadIdx.x < NB_SCAN) g_partial[threadIdx.x] = 0ULL;
    } else {
        int i = blockIdx.x * 1024 + threadIdx.x;
        if (i < N) { g_expsum[i] = 0.f; g_count[i] = 0; g_fill[i] = 0; }
    }
}

__device__ __forceinline__ int load_idx(const void* eidx, long long i) {
    if (g_flag) return (int)((const long long*)eidx)[i];
    return ((const int*)eidx)[i];
}

// in-degree histogram
__global__ void hist_kernel(const void* __restrict__ eidx, int E) {
    int e = blockIdx.x * blockDim.x + threadIdx.x;
    if (e >= E) return;
    int d = load_idx(eidx, (long long)E + e);
    atomicAdd(&g_count[d], 1);
}

// ---------------- single-launch decoupled-lookback scan ----------------
// 98 blocks <= 148 SMs: all resident in wave 1, lookback cannot deadlock.
__global__ void scan_kernel(int N) {
    __shared__ int s[1024];
    __shared__ unsigned pre;
    int t = threadIdx.x, b = blockIdx.x;
    int i = b * 1024 + t;
    int v = (i < N) ? g_count[i] : 0;
    s[t] = v;
    __syncthreads();
    for (int d2 = 1; d2 < 1024; d2 <<= 1) {
        int w = (t >= d2) ? s[t - d2] : 0;
        __syncthreads();
        s[t] += w;
        __syncthreads();
    }
    int total = s[1023];
    if (t == 0) {
        unsigned long long pk =
            ((unsigned long long)(b == 0 ? 2u : 1u) << 32) | (unsigned)total;
        atomicExch(&g_partial[b], pk);
        unsigned acc = 0;
        if (b > 0) {
            int j = b - 1;
            while (true) {
                unsigned long long p = atomicAdd(&g_partial[j], 0ULL);
                unsigned st = (unsigned)(p >> 32);
                if (st == 0) continue;
                acc += (unsigned)p;
                if (st == 2) break;
                j--;
            }
            atomicExch(&g_partial[b],
                       ((unsigned long long)2u << 32) | (unsigned)(acc + total));
        }
        pre = acc;
    }
    __syncthreads();
    if (i < N) g_off[i + 1] = s[t] + (int)pre;
    if (b == 0 && t == 0) g_off[0] = 0;
}

// fill CSR buckets: {src*64 (premultiplied row offset), exp(attr)} + expsum
__global__ void bucket_kernel(const void* __restrict__ eidx,
                              const float* __restrict__ attr, int E) {
    int e = blockIdx.x * blockDim.x + threadIdx.x;
    if (e >= E) return;
    int s = load_idx(eidx, e);
    int d = load_idx(eidx, (long long)E + e);
    float ex = __expf(attr[e]);
    int pos = g_off[d] + atomicAdd(&g_fill[d], 1);
    g_edge[pos] = make_float2(__int_as_float(s * 64), ex);
    atomicAdd(&g_expsum[d], ex);
}

// ---------------- GEMM: XW[n][o] = sum_k X[n][k] * W[o][k] ----------------
// (round-3 proven) 128x64 tile, KC=64 chunks, 512 threads, f32x2 FMA.
// Thread (rg=tid>>4, cg=tid&15): rows 4rg..4rg+3, cols cg+16j (j=0..3).
template <int CIN>
__global__ void __launch_bounds__(512, 2) gemm_kernel(
    const float* __restrict__ X, const float* __restrict__ W,
    float* __restrict__ XW, int N) {
    __shared__ float xs[128][64];                  // [row][k] 32KB
    __shared__ unsigned long long wt2[32][64];     // [k-pair][out] 16KB
    const int tid = threadIdx.x;
    const int cg = tid & 15;
    const int rg = tid >> 4;
    const int base = blockIdx.x * 128;

    unsigned long long acc[4][4] = {};

    for (int kc = 0; kc < CIN; kc += 64) {
        for (int idx = tid; idx < 64 * 16; idx += 512) {
            int o = idx & 63, k4 = idx >> 6;
            float4 w = *(const float4*)(W + o * CIN + kc + k4 * 4);
            unsigned long long p0, p1;
            asm("mov.b64 %0, {%1, %2};" : "=l"(p0) : "f"(w.x), "f"(w.y));
            asm("mov.b64 %0, {%1, %2};" : "=l"(p1) : "f"(w.z), "f"(w.w));
            wt2[2 * k4 + 0][o] = p0;
            wt2[2 * k4 + 1][o] = p1;
        }
        for (int idx = tid; idx < 128 * 16; idx += 512) {
            int r = idx >> 4, k4 = idx & 15;
            int n = base + r;
            float4 v = (n < N) ? *(const float4*)(X + (size_t)n * CIN + kc + k4 * 4)
                               : make_float4(0.f, 0.f, 0.f, 0.f);
            *(float4*)&xs[r][k4 * 4] = v;
        }
        __syncthreads();

#pragma unroll
        for (int k4 = 0; k4 < 16; k4++) {
            ulonglong2 b[4];
#pragma unroll
            for (int j = 0; j < 4; j++) {
                b[j].x = wt2[2 * k4 + 0][cg + 16 * j];
                b[j].y = wt2[2 * k4 + 1][cg + 16 * j];
            }
#pragma unroll
            for (int i = 0; i < 4; i++) {
                ulonglong2 a = *(const ulonglong2*)&xs[rg * 4 + i][k4 * 4];
#pragma unroll
                for (int j = 0; j < 4; j++) {
                    ffma2(acc[i][j], a.x, b[j].x);
                    ffma2(acc[i][j], a.y, b[j].y);
                }
            }
        }
        __syncthreads();
    }

#pragma unroll
    for (int i = 0; i < 4; i++) {
        int n = base + rg * 4 + i;
        if (n < N) {
#pragma unroll
            for (int j = 0; j < 4; j++)
                XW[(size_t)n * 64 + cg + 16 * j] = f32x2_hsum(acc[i][j]);
        }
    }
}

// ---------------- fused aggregate + softmax-div + self + bias + sigmoid ----
// warp per node in [n0,n1); lane l owns cols 2l,2l+1. fp32 throughout.
__global__ void __launch_bounds__(256) aggregate_kernel(
    const float* __restrict__ XW, const float* __restrict__ b,
    float* __restrict__ H, int n0, int n1) {
    int n = n0 + ((blockIdx.x * blockDim.x + threadIdx.x) >> 5);
    int lane = threadIdx.x & 31;
    if (n >= n1) return;
    int i0 = g_off[n], i1 = g_off[n + 1];
    int c = lane * 2;
    const float* XWc = XW + c;
    float a0 = 0.f, a1 = 0.f, c0 = 0.f, c1 = 0.f;
    int i = i0;
    for (; i + 4 <= i1; i += 4) {
        float2 e0 = g_edge[i + 0];
        float2 e1 = g_edge[i + 1];
        float2 e2 = g_edge[i + 2];
        float2 e3 = g_edge[i + 3];
        float2 v0 = *(const float2*)(XWc + __float_as_int(e0.x));
        float2 v1 = *(const float2*)(XWc + __float_as_int(e1.x));
        float2 v2 = *(const float2*)(XWc + __float_as_int(e2.x));
        float2 v3 = *(const float2*)(XWc + __float_as_int(e3.x));
        a0 = fmaf(e0.y, v0.x, a0); a1 = fmaf(e0.y, v0.y, a1);
        c0 = fmaf(e1.y, v1.x, c0); c1 = fmaf(e1.y, v1.y, c1);
        a0 = fmaf(e2.y, v2.x, a0); a1 = fmaf(e2.y, v2.y, a1);
        c0 = fmaf(e3.y, v3.x, c0); c1 = fmaf(e3.y, v3.y, c1);
    }
    for (; i < i1; i++) {
        float2 e = g_edge[i];
        float2 v = *(const float2*)(XWc + __float_as_int(e.x));
        a0 = fmaf(e.y, v.x, a0); a1 = fmaf(e.y, v.y, a1);
    }
    a0 += c0; a1 += c1;
    float inv = (i1 > i0) ? 1.f / g_expsum[n] : 0.f;
    float2 xn = *(const float2*)(XWc + n * 64);
    float o0 = a0 * inv + xn.x + b[c];
    float o1 = a1 * inv + xn.y + b[c + 1];
    float2 r;
    r.x = 1.f / (1.f + __expf(-o0));
    r.y = 1.f / (1.f + __expf(-o1));
    *(float2*)(H + (size_t)n * 64 + c) = r;
}

// ---------------- launch ----------------
extern "C" void kernel_launch(void* const* d_in, const int* in_sizes, int n_in,
                              void* d_out, int out_size) {
    const float* x    = (const float*)d_in[0];
    const void*  eidx = d_in[1];
    const float* attr = (const float*)d_in[2];
    const float* W1   = (const float*)d_in[3];
    const float* b1   = (const float*)d_in[4];
    const float* W2   = (const float*)d_in[5];
    const float* b2   = (const float*)d_in[6];
    float* out = (float*)d_out;

    int E = in_sizes[2];           // 1,600,000
    int N = out_size / 64;         // 100,000

    void* p;
    cudaGetSymbolAddress(&p, g_xw);   float* xw  = (float*)p;
    cudaGetSymbolAddress(&p, g_xw2);  float* xw2 = (float*)p;
    cudaGetSymbolAddress(&p, g_h1);   float* h1  = (float*)p;

    int eb = (E + 255) / 256;
    int nb = (N + 1023) / 1024;    // 98 scan blocks

    cudaStream_t s1;
    cudaStreamCreate(&s1);
    cudaEvent_t evFork, evPre, evLo, evHi, evG2;
    cudaEventCreateWithFlags(&evFork, cudaEventDisableTiming);
    cudaEventCreateWithFlags(&evPre, cudaEventDisableTiming);
    cudaEventCreateWithFlags(&evLo, cudaEventDisableTiming);
    cudaEventCreateWithFlags(&evHi, cudaEventDisableTiming);
    cudaEventCreateWithFlags(&evG2, cudaEventDisableTiming);

    cudaEventRecord(evFork, 0);
    cudaStreamWaitEvent(s1, evFork, 0);

    // s1: preprocessing (4 launches, shared by both layers)
    zero_detect_kernel<<<nb + 1, 1024, 0, s1>>>((const int*)eidx, N);
    hist_kernel<<<eb, 256, 0, s1>>>(eidx, E);
    scan_kernel<<<nb, 1024, 0, s1>>>(N);
    bucket_kernel<<<eb, 256, 0, s1>>>(eidx, attr, E);
    cudaEventRecord(evPre, s1);

    // split point: multiple of 128 (GEMM tile)
    int half = ((N / 2) / 128) * 128;          // 49920
    int hiN  = N - half;

    // main: layer-1 GEMM overlaps preprocessing
    gemm_kernel<128><<<(N + 127) / 128, 512>>>(x, W1, xw, N);

    // main: agg1 in two halves (join preprocessing first)
    cudaStreamWaitEvent(0, evPre, 0);
    aggregate_kernel<<<(half + 7) / 8, 256>>>(xw, b1, h1, 0, half);
    cudaEventRecord(evLo, 0);
    aggregate_kernel<<<(hiN + 7) / 8, 256>>>(xw, b1, h1, half, N);
    cudaEventRecord(evHi, 0);

    // s1: gemm2 halves pipelined against agg1 (writes xw2 — no race with agg1)
    cudaStreamWaitEvent(s1, evLo, 0);
    gemm_kernel<64><<<half / 128, 512, 0, s1>>>(h1, W2, xw2, half);
    cudaStreamWaitEvent(s1, evHi, 0);
    gemm_kernel<64><<<(hiN + 127) / 128, 512, 0, s1>>>(
        h1 + (size_t)half * 64, W2, xw2 + (size_t)half * 64, hiN);
    cudaEventRecord(evG2, s1);

    // main: final aggregate
    cudaStreamWaitEvent(0, evG2, 0);
    aggregate_kernel<<<(N + 7) / 8, 256>>>(xw2, b2, out, 0, N);
}

// round 7
// speedup vs baseline: 1.1433x; 1.1433x over previous
#include <cuda_runtime.h>
#include <cuda_bf16.h>

#define N_MAX 100000
#define E_MAX 1600000
#define NB_SCAN 128

// ---------------- device scratch ----------------
__device__ int    g_flag;                 // 1 = edge_index is int64
__device__ float  g_expsum[N_MAX];
__device__ int    g_count[N_MAX];
__device__ int    g_fill[N_MAX];
__device__ int    g_off[N_MAX + 1];
__device__ unsigned long long g_partial[NB_SCAN];   // lookback state
__device__ float2 g_edge[E_MAX];          // {bits(src*64), exp(attr)} CSR by dst
__device__ float  g_xw[N_MAX * 64];
__device__ float  g_h1[N_MAX * 64];

// ---------------- f32x2 packed fma ----------------
__device__ __forceinline__ void ffma2(unsigned long long& d,
                                      unsigned long long a,
                                      unsigned long long b) {
    asm("fma.rn.f32x2 %0, %1, %2, %0;" : "+l"(d) : "l"(a), "l"(b));
}
__device__ __forceinline__ float f32x2_hsum(unsigned long long v) {
    unsigned int lo, hi;
    asm("mov.b64 {%0, %1}, %2;" : "=r"(lo), "=r"(hi) : "l"(v));
    return __uint_as_float(lo) + __uint_as_float(hi);
}

// ---------------- fused zero + dtype detect ----------------
__global__ void zero_detect_kernel(const int* __restrict__ p, int N) {
    if (blockIdx.x == gridDim.x - 1) {
        __shared__ int cnt;
        if (threadIdx.x == 0) cnt = 0;
        __syncthreads();
        int nz = 0;
        for (int i = threadIdx.x; i < 4096; i += blockDim.x)
            if (p[2 * i + 1] != 0) nz++;
        atomicAdd(&cnt, nz);
        __syncthreads();
        if (threadIdx.x == 0) g_flag = (cnt < 64) ? 1 : 0;
        if (threadIdx.x < NB_SCAN) g_partial[threadIdx.x] = 0ULL;
    } else {
        int i = blockIdx.x * 1024 + threadIdx.x;
        if (i < N) { g_expsum[i] = 0.f; g_count[i] = 0; g_fill[i] = 0; }
    }
}

__device__ __forceinline__ int load_idx(const void* eidx, long long i) {
    if (g_flag) return (int)((const long long*)eidx)[i];
    return ((const int*)eidx)[i];
}

// in-degree histogram
__global__ void hist_kernel(const void* __restrict__ eidx, int E) {
    int e = blockIdx.x * blockDim.x + threadIdx.x;
    if (e >= E) return;
    int d = load_idx(eidx, (long long)E + e);
    atomicAdd(&g_count[d], 1);
}

// ---------------- single-launch decoupled-lookback scan ----------------
// 98 blocks <= 148 SMs: all resident in wave 1, lookback cannot deadlock.
__global__ void scan_kernel(int N) {
    __shared__ int s[1024];
    __shared__ unsigned pre;
    int t = threadIdx.x, b = blockIdx.x;
    int i = b * 1024 + t;
    int v = (i < N) ? g_count[i] : 0;
    s[t] = v;
    __syncthreads();
    for (int d2 = 1; d2 < 1024; d2 <<= 1) {
        int w = (t >= d2) ? s[t - d2] : 0;
        __syncthreads();
        s[t] += w;
        __syncthreads();
    }
    int total = s[1023];
    if (t == 0) {
        unsigned long long pk =
            ((unsigned long long)(b == 0 ? 2u : 1u) << 32) | (unsigned)total;
        atomicExch(&g_partial[b], pk);
        unsigned acc = 0;
        if (b > 0) {
            int j = b - 1;
            while (true) {
                unsigned long long p = atomicAdd(&g_partial[j], 0ULL);
                unsigned st = (unsigned)(p >> 32);
                if (st == 0) continue;
                acc += (unsigned)p;
                if (st == 2) break;
                j--;
            }
            atomicExch(&g_partial[b],
                       ((unsigned long long)2u << 32) | (unsigned)(acc + total));
        }
        pre = acc;
    }
    __syncthreads();
    if (i < N) g_off[i + 1] = s[t] + (int)pre;
    if (b == 0 && t == 0) g_off[0] = 0;
}

// fill CSR buckets: {src*64 (premultiplied row offset), exp(attr)} + expsum
__global__ void bucket_kernel(const void* __restrict__ eidx,
                              const float* __restrict__ attr, int E) {
    int e = blockIdx.x * blockDim.x + threadIdx.x;
    if (e >= E) return;
    int s = load_idx(eidx, e);
    int d = load_idx(eidx, (long long)E + e);
    float ex = __expf(attr[e]);
    int pos = g_off[d] + atomicAdd(&g_fill[d], 1);
    g_edge[pos] = make_float2(__int_as_float(s * 64), ex);
    atomicAdd(&g_expsum[d], ex);
}

// ---------------- GEMM: XW[n][o] = sum_k X[n][k] * W[o][k] ----------------
// (round-3 proven) 128x64 tile, KC=64 chunks, 512 threads, f32x2 FMA.
// Thread (rg=tid>>4, cg=tid&15): rows 4rg..4rg+3, cols cg+16j (j=0..3).
template <int CIN>
__global__ void __launch_bounds__(512, 2) gemm_kernel(
    const float* __restrict__ X, const float* __restrict__ W,
    float* __restrict__ XW, int N) {
    __shared__ float xs[128][64];                  // [row][k] 32KB
    __shared__ unsigned long long wt2[32][64];     // [k-pair][out] 16KB
    const int tid = threadIdx.x;
    const int cg = tid & 15;
    const int rg = tid >> 4;
    const int base = blockIdx.x * 128;

    unsigned long long acc[4][4] = {};

    for (int kc = 0; kc < CIN; kc += 64) {
        for (int idx = tid; idx < 64 * 16; idx += 512) {
            int o = idx & 63, k4 = idx >> 6;
            float4 w = *(const float4*)(W + o * CIN + kc + k4 * 4);
            unsigned long long p0, p1;
            asm("mov.b64 %0, {%1, %2};" : "=l"(p0) : "f"(w.x), "f"(w.y));
            asm("mov.b64 %0, {%1, %2};" : "=l"(p1) : "f"(w.z), "f"(w.w));
            wt2[2 * k4 + 0][o] = p0;
            wt2[2 * k4 + 1][o] = p1;
        }
        for (int idx = tid; idx < 128 * 16; idx += 512) {
            int r = idx >> 4, k4 = idx & 15;
            int n = base + r;
            float4 v = (n < N) ? *(const float4*)(X + (size_t)n * CIN + kc + k4 * 4)
                               : make_float4(0.f, 0.f, 0.f, 0.f);
            *(float4*)&xs[r][k4 * 4] = v;
        }
        __syncthreads();

#pragma unroll
        for (int k4 = 0; k4 < 16; k4++) {
            ulonglong2 b[4];
#pragma unroll
            for (int j = 0; j < 4; j++) {
                b[j].x = wt2[2 * k4 + 0][cg + 16 * j];
                b[j].y = wt2[2 * k4 + 1][cg + 16 * j];
            }
#pragma unroll
            for (int i = 0; i < 4; i++) {
                ulonglong2 a = *(const ulonglong2*)&xs[rg * 4 + i][k4 * 4];
#pragma unroll
                for (int j = 0; j < 4; j++) {
                    ffma2(acc[i][j], a.x, b[j].x);
                    ffma2(acc[i][j], a.y, b[j].y);
                }
            }
        }
        __syncthreads();
    }

#pragma unroll
    for (int i = 0; i < 4; i++) {
        int n = base + rg * 4 + i;
        if (n < N) {
#pragma unroll
            for (int j = 0; j < 4; j++)
                XW[(size_t)n * 64 + cg + 16 * j] = f32x2_hsum(acc[i][j]);
        }
    }
}

// ---------------- fused aggregate + softmax-div + self + bias + sigmoid ----
// TWO nodes per warp: half-warp (16 lanes x float4) owns one node's 64 cols.
// Edge src offsets are premultiplied by 64 at bucket time.
__global__ void __launch_bounds__(256) aggregate_kernel(
    const float* __restrict__ XW, const float* __restrict__ b,
    float* __restrict__ H, int N) {
    int warp = (blockIdx.x * blockDim.x + threadIdx.x) >> 5;
    int lane = threadIdx.x & 31;
    int half = lane >> 4;              // 0 or 1
    int hl   = lane & 15;
    int n = warp * 2 + half;
    if (n >= N) return;
    int i0 = g_off[n], i1 = g_off[n + 1];
    int c = hl * 4;
    const float* XWc = XW + c;
    float4 a = make_float4(0.f, 0.f, 0.f, 0.f);
    float4 a2 = make_float4(0.f, 0.f, 0.f, 0.f);
    int i = i0;
    for (; i + 2 <= i1; i += 2) {
        float2 e0 = g_edge[i];
        float2 e1 = g_edge[i + 1];
        float4 v0 = *(const float4*)(XWc + __float_as_int(e0.x));
        float4 v1 = *(const float4*)(XWc + __float_as_int(e1.x));
        a.x = fmaf(e0.y, v0.x, a.x);   a.y = fmaf(e0.y, v0.y, a.y);
        a.z = fmaf(e0.y, v0.z, a.z);   a.w = fmaf(e0.y, v0.w, a.w);
        a2.x = fmaf(e1.y, v1.x, a2.x); a2.y = fmaf(e1.y, v1.y, a2.y);
        a2.z = fmaf(e1.y, v1.z, a2.z); a2.w = fmaf(e1.y, v1.w, a2.w);
    }
    if (i < i1) {
        float2 e = g_edge[i];
        float4 v = *(const float4*)(XWc + __float_as_int(e.x));
        a.x = fmaf(e.y, v.x, a.x); a.y = fmaf(e.y, v.y, a.y);
        a.z = fmaf(e.y, v.z, a.z); a.w = fmaf(e.y, v.w, a.w);
    }
    a.x += a2.x; a.y += a2.y; a.z += a2.z; a.w += a2.w;
    float inv = (i1 > i0) ? 1.f / g_expsum[n] : 0.f;
    float4 xn = *(const float4*)(XWc + n * 64);
    float4 bb = *(const float4*)(b + c);
    float o0 = fmaf(a.x, inv, xn.x) + bb.x;
    float o1 = fmaf(a.y, inv, xn.y) + bb.y;
    float o2 = fmaf(a.z, inv, xn.z) + bb.z;
    float o3 = fmaf(a.w, inv, xn.w) + bb.w;
    float4 r;
    r.x = 1.f / (1.f + __expf(-o0));
    r.y = 1.f / (1.f + __expf(-o1));
    r.z = 1.f / (1.f + __expf(-o2));
    r.w = 1.f / (1.f + __expf(-o3));
    *(float4*)(H + (size_t)n * 64 + c) = r;
}

// ---------------- launch ----------------
extern "C" void kernel_launch(void* const* d_in, const int* in_sizes, int n_in,
                              void* d_out, int out_size) {
    const float* x    = (const float*)d_in[0];
    const void*  eidx = d_in[1];
    const float* attr = (const float*)d_in[2];
    const float* W1   = (const float*)d_in[3];
    const float* b1   = (const float*)d_in[4];
    const float* W2   = (const float*)d_in[5];
    const float* b2   = (const float*)d_in[6];
    float* out = (float*)d_out;

    int E = in_sizes[2];           // 1,600,000
    int N = out_size / 64;         // 100,000

    void* p;
    cudaGetSymbolAddress(&p, g_xw);   float* xw = (float*)p;
    cudaGetSymbolAddress(&p, g_h1);   float* h1 = (float*)p;

    int eb = (E + 255) / 256;
    int nb = (N + 1023) / 1024;    // 98 scan blocks

    cudaStream_t s1;
    cudaStreamCreate(&s1);
    cudaEvent_t evFork, evPre;
    cudaEventCreateWithFlags(&evFork, cudaEventDisableTiming);
    cudaEventCreateWithFlags(&evPre, cudaEventDisableTiming);

    cudaEventRecord(evFork, 0);
    cudaStreamWaitEvent(s1, evFork, 0);

    // s1: preprocessing (4 launches, shared by both layers)
    zero_detect_kernel<<<nb + 1, 1024, 0, s1>>>((const int*)eidx, N);
    hist_kernel<<<eb, 256, 0, s1>>>(eidx, E);
    scan_kernel<<<nb, 1024, 0, s1>>>(N);
    bucket_kernel<<<eb, 256, 0, s1>>>(eidx, attr, E);
    cudaEventRecord(evPre, s1);

    int gemm_blocks = (N + 127) / 128;
    int agg_blocks  = (N + 15) / 16;   // 2 nodes/warp, 8 warps/block

    // main: layer-1 GEMM overlaps preprocessing
    gemm_kernel<128><<<gemm_blocks, 512>>>(x, W1, xw, N);

    // join, then the serial tail (proven fastest structure)
    cudaStreamWaitEvent(0, evPre, 0);
    aggregate_kernel<<<agg_blocks, 256>>>(xw, b1, h1, N);
    gemm_kernel<64><<<gemm_blocks, 512>>>(h1, W2, xw, N);
    aggregate_kernel<<<agg_blocks, 256>>>(xw, b2, out, N);
}